// round 1
// baseline (speedup 1.0000x reference)
#include <cuda_runtime.h>
#include <math.h>

#define N_NODES  100000
#define N_EDGES  400000
#define N_GRAPHS 4000
#define D        70

// ---------------- scratch (device globals; no allocation allowed) ----------
__device__ float g_h[N_NODES * D];          // node features, updated in place
__device__ float g_agg[N_NODES * 4 * D];    // [mean|min|max|std] per node (K=280)
__device__ float g_amp[N_NODES];            // amplification scaler per node
__device__ int   g_cnt[N_NODES];            // in-degree histogram
__device__ int   g_cur[N_NODES];            // scatter cursors
__device__ int   g_off[N_NODES + 1];        // CSR offsets (by dst)
__device__ int   g_sorted[N_EDGES];         // edge ids grouped by dst
__device__ float g_gsum[N_GRAPHS * D];
__device__ float g_gcnt[N_GRAPHS];

__constant__ int c_atom_off[9] = {0, 119, 124, 136, 148, 158, 164, 170, 172};

#define AVG_LOG_F 1.2465355243460002f
#define INV_BN    0.9999950000374997f   // 1/sqrt(1 + 1e-5)

// ---------------- zero scratch --------------------------------------------
__global__ void zero_kernel() {
    int i = blockIdx.x * blockDim.x + threadIdx.x;
    int stride = gridDim.x * blockDim.x;
    for (int j = i; j < N_NODES; j += stride) { g_cnt[j] = 0; g_cur[j] = 0; }
    for (int j = i; j < N_GRAPHS * D; j += stride) g_gsum[j] = 0.f;
    for (int j = i; j < N_GRAPHS; j += stride) g_gcnt[j] = 0.f;
}

// ---------------- atom encoder: h[n][f] = sum_j emb[x[n][j]+off_j][f] -----
__global__ void atom_kernel(const int* __restrict__ x, const float* __restrict__ emb) {
    int n = blockIdx.x * blockDim.y + threadIdx.y;
    int f = threadIdx.x;                 // 0..69
    if (n >= N_NODES) return;
    float s = 0.f;
#pragma unroll
    for (int j = 0; j < 9; j++) {
        int idx = x[n * 9 + j] + c_atom_off[j];
        s += emb[idx * D + f];
    }
    g_h[n * D + f] = s;
}

// ---------------- CSR build by dst ----------------------------------------
__global__ void hist_kernel(const int* __restrict__ ei) {
    int e = blockIdx.x * blockDim.x + threadIdx.x;
    if (e < N_EDGES) atomicAdd(&g_cnt[ei[N_EDGES + e]], 1);
}

__global__ void scan_kernel() {   // single block, 1024 threads
    __shared__ int s[1024];
    int t = threadIdx.x;
    const int chunk = (N_NODES + 1023) / 1024;   // 98
    int start = t * chunk;
    int end = start + chunk; if (end > N_NODES) end = N_NODES;
    if (start > N_NODES) start = N_NODES;
    int sum = 0;
    for (int i = start; i < end; i++) sum += g_cnt[i];
    s[t] = sum;
    __syncthreads();
    for (int d = 1; d < 1024; d <<= 1) {
        int add = (t >= d) ? s[t - d] : 0;
        __syncthreads();
        s[t] += add;
        __syncthreads();
    }
    int base = (t == 0) ? 0 : s[t - 1];
    for (int i = start; i < end; i++) { g_off[i] = base; base += g_cnt[i]; }
    if (t == 1023) g_off[N_NODES] = s[1023];
}

__global__ void scatter_kernel(const int* __restrict__ ei) {
    int e = blockIdx.x * blockDim.x + threadIdx.x;
    if (e < N_EDGES) {
        int d = ei[N_EDGES + e];
        int p = atomicAdd(&g_cur[d], 1);
        g_sorted[g_off[d] + p] = e;
    }
}

// ---------------- per-node aggregation (one warp per node) ----------------
__global__ void agg_kernel(const int* __restrict__ ei, const float* __restrict__ ea) {
    int gtid = blockIdx.x * blockDim.x + threadIdx.x;
    int node = gtid >> 5;
    int lane = gtid & 31;
    if (node >= N_NODES) return;

    const float* hrow = g_h + (size_t)node * D;
    float hd0 = hrow[lane];
    float hd1 = hrow[lane + 32];
    float hd2 = (lane < 6) ? hrow[lane + 64] : 0.f;

    int beg = g_off[node], end = g_off[node + 1];
    float s0 = 0.f, s1 = 0.f, s2 = 0.f;
    float q0 = 0.f, q1 = 0.f, q2 = 0.f;
    float mn0 = 3.4e38f, mn1 = 3.4e38f, mn2 = 3.4e38f;
    float mx0 = 0.f, mx1 = 0.f, mx2 = 0.f;  // messages are ReLU'd (>= 0)

    for (int p = beg; p < end; p++) {
        int e = g_sorted[p];
        int sn = ei[e];  // src
        const float* hs = g_h + (size_t)sn * D;
        const float* er = ea + (size_t)e * D;
        float m0 = fmaxf(hd0 + hs[lane]      + er[lane],      0.f);
        float m1 = fmaxf(hd1 + hs[lane + 32] + er[lane + 32], 0.f);
        float m2 = 0.f;
        if (lane < 6) m2 = fmaxf(hd2 + hs[lane + 64] + er[lane + 64], 0.f);
        s0 += m0; q0 += m0 * m0; mn0 = fminf(mn0, m0); mx0 = fmaxf(mx0, m0);
        s1 += m1; q1 += m1 * m1; mn1 = fminf(mn1, m1); mx1 = fmaxf(mx1, m1);
        s2 += m2; q2 += m2 * m2; mn2 = fminf(mn2, m2); mx2 = fmaxf(mx2, m2);
    }
    int cnt = end - beg;
    float cntf = (cnt > 0) ? (float)cnt : 1.f;

    float me0 = s0 / cntf, me1 = s1 / cntf, me2 = s2 / cntf;
    float v0 = fmaxf(q0 / cntf - me0 * me0, 0.f);
    float v1 = fmaxf(q1 / cntf - me1 * me1, 0.f);
    float v2 = fmaxf(q2 / cntf - me2 * me2, 0.f);
    float sd0 = sqrtf(v0 + 1e-5f), sd1 = sqrtf(v1 + 1e-5f), sd2 = sqrtf(v2 + 1e-5f);
    if (cnt == 0) { mn0 = mn1 = mn2 = 0.f; mx0 = mx1 = mx2 = 0.f; }

    float* a = g_agg + (size_t)node * (4 * D);
    a[lane]               = me0; a[lane + 32]           = me1;
    a[D + lane]           = mn0; a[D + lane + 32]       = mn1;
    a[2 * D + lane]       = mx0; a[2 * D + lane + 32]   = mx1;
    a[3 * D + lane]       = sd0; a[3 * D + lane + 32]   = sd1;
    if (lane < 6) {
        a[lane + 64]         = me2;
        a[D + lane + 64]     = mn2;
        a[2 * D + lane + 64] = mx2;
        a[3 * D + lane + 64] = sd2;
    }
    if (lane == 0) g_amp[node] = logf(cntf + 1.f) / AVG_LOG_F;
}

// ---------------- GEMM + scalers + bias + BN + ReLU + residual ------------
// c = agg@W0 + amp*(agg@W1) + (agg@W2)/amp + b ; h += relu(c*invbn*gamma + beta)
#define BM 64
#define BK 40
__global__ __launch_bounds__(280, 2)
void gemm_kernel(const float* __restrict__ W, const float* __restrict__ b,
                 const float* __restrict__ gamma, const float* __restrict__ beta) {
    __shared__ float As[BM][BK];
    __shared__ float Ws[3][BK][D];
    int tx = threadIdx.x;   // 0..69 (output column)
    int ty = threadIdx.y;   // 0..3  (row group)
    int t = ty * 70 + tx;
    int row0 = blockIdx.x * BM;

    float acc0[16], acc1[16], acc2[16];
#pragma unroll
    for (int r = 0; r < 16; r++) { acc0[r] = 0.f; acc1[r] = 0.f; acc2[r] = 0.f; }

    for (int kt = 0; kt < 7; kt++) {
        int k0 = kt * BK;
        for (int idx = t; idx < BM * BK; idx += 280) {
            int r = idx / BK, kk = idx - r * BK;
            int gr = row0 + r;
            As[r][kk] = (gr < N_NODES) ? g_agg[(size_t)gr * 280 + k0 + kk] : 0.f;
        }
        for (int idx = t; idx < 3 * BK * D; idx += 280) {
            int p = idx / (BK * D);
            int rem = idx - p * BK * D;
            int r = rem / D, j = rem - r * D;
            Ws[p][r][j] = W[(size_t)(p * 280 + k0 + r) * D + j];
        }
        __syncthreads();
#pragma unroll
        for (int k4 = 0; k4 < BK / 4; k4++) {
            float w00 = Ws[0][4 * k4 + 0][tx], w01 = Ws[0][4 * k4 + 1][tx],
                  w02 = Ws[0][4 * k4 + 2][tx], w03 = Ws[0][4 * k4 + 3][tx];
            float w10 = Ws[1][4 * k4 + 0][tx], w11 = Ws[1][4 * k4 + 1][tx],
                  w12 = Ws[1][4 * k4 + 2][tx], w13 = Ws[1][4 * k4 + 3][tx];
            float w20 = Ws[2][4 * k4 + 0][tx], w21 = Ws[2][4 * k4 + 1][tx],
                  w22 = Ws[2][4 * k4 + 2][tx], w23 = Ws[2][4 * k4 + 3][tx];
#pragma unroll
            for (int r = 0; r < 16; r++) {
                float4 a = *reinterpret_cast<const float4*>(&As[ty * 16 + r][4 * k4]);
                acc0[r] += a.x * w00 + a.y * w01 + a.z * w02 + a.w * w03;
                acc1[r] += a.x * w10 + a.y * w11 + a.z * w12 + a.w * w13;
                acc2[r] += a.x * w20 + a.y * w21 + a.z * w22 + a.w * w23;
            }
        }
        __syncthreads();
    }

    float bj = b[tx], gj = gamma[tx], btj = beta[tx];
#pragma unroll
    for (int r = 0; r < 16; r++) {
        int gr = row0 + ty * 16 + r;
        if (gr < N_NODES) {
            float amp = g_amp[gr];
            float c = acc0[r] + amp * acc1[r] + acc2[r] / amp + bj;
            float hn = fmaxf(c * INV_BN * gj + btj, 0.f);
            g_h[(size_t)gr * D + tx] += hn;   // residual
        }
    }
}

// ---------------- global mean pool ----------------------------------------
__global__ void pool_kernel(const int* __restrict__ batch) {
    int n = blockIdx.x * blockDim.y + threadIdx.y;
    int f = threadIdx.x;
    if (n >= N_NODES) return;
    int gi = batch[n];
    atomicAdd(&g_gsum[gi * D + f], g_h[(size_t)n * D + f]);
    if (f == 0) atomicAdd(&g_gcnt[gi], 1.f);
}

// ---------------- final MLP 70->35->17->1 ---------------------------------
__global__ void mlp_kernel(const float* __restrict__ w1, const float* __restrict__ b1,
                           const float* __restrict__ w2, const float* __restrict__ b2,
                           const float* __restrict__ w3, const float* __restrict__ b3,
                           float* __restrict__ out) {
    __shared__ float sg[70], t1[35], t2[17];
    int gi = blockIdx.x;
    int t = threadIdx.x;
    if (t < 70) {
        float c = fmaxf(g_gcnt[gi], 1.f);
        sg[t] = g_gsum[gi * D + t] / c;
    }
    __syncthreads();
    if (t < 35) {
        float s = b1[t];
        for (int k = 0; k < 70; k++) s += sg[k] * w1[k * 35 + t];
        t1[t] = fmaxf(s, 0.f);
    }
    __syncthreads();
    if (t < 17) {
        float s = b2[t];
        for (int k = 0; k < 35; k++) s += t1[k] * w2[k * 17 + t];
        t2[t] = fmaxf(s, 0.f);
    }
    __syncthreads();
    if (t == 0) {
        float s = b3[0];
        for (int k = 0; k < 17; k++) s += t2[k] * w3[k];
        out[gi] = s;
    }
}

// ---------------- launcher -------------------------------------------------
extern "C" void kernel_launch(void* const* d_in, const int* in_sizes, int n_in,
                              void* d_out, int out_size) {
    const int*   x      = (const int*)d_in[0];
    const int*   ei     = (const int*)d_in[1];
    const float* ea     = (const float*)d_in[2];
    const int*   batch  = (const int*)d_in[3];
    const float* emb    = (const float*)d_in[4];
    const float* post_w = (const float*)d_in[5];
    const float* post_b = (const float*)d_in[6];
    const float* gamma  = (const float*)d_in[7];
    const float* beta   = (const float*)d_in[8];
    const float* w1 = (const float*)d_in[9];
    const float* b1 = (const float*)d_in[10];
    const float* w2 = (const float*)d_in[11];
    const float* b2 = (const float*)d_in[12];
    const float* w3 = (const float*)d_in[13];
    const float* b3 = (const float*)d_in[14];
    float* out = (float*)d_out;

    zero_kernel<<<512, 256>>>();
    atom_kernel<<<(N_NODES + 3) / 4, dim3(70, 4)>>>(x, emb);
    hist_kernel<<<(N_EDGES + 255) / 256, 256>>>(ei);
    scan_kernel<<<1, 1024>>>();
    scatter_kernel<<<(N_EDGES + 255) / 256, 256>>>(ei);

    for (int l = 0; l < 4; l++) {
        agg_kernel<<<(N_NODES * 32 + 255) / 256, 256>>>(ei, ea);
        gemm_kernel<<<(N_NODES + BM - 1) / BM, dim3(70, 4)>>>(
            post_w + (size_t)l * 840 * 70, post_b + l * 70,
            gamma + l * 70, beta + l * 70);
    }

    pool_kernel<<<(N_NODES + 3) / 4, dim3(70, 4)>>>(batch);
    mlp_kernel<<<N_GRAPHS, 70>>>(w1, b1, w2, b2, w3, b3, out);
}

// round 4
// speedup vs baseline: 1.7108x; 1.7108x over previous
#include <cuda_runtime.h>
#include <math.h>

#define N_NODES  100000
#define N_EDGES  400000
#define N_GRAPHS 4000
#define D        70
#define NP       240          // padded GEMM N (3 panels x 80)
#define KDIM     280

// ---------------- scratch (device globals) ---------------------------------
__device__ float g_h[N_NODES * D];
__device__ float g_agg[N_NODES * 4 * D];      // [mean|min|max|std], K=280
__device__ float g_amp[N_NODES];
__device__ int   g_cnt[N_NODES];
__device__ int   g_cur[N_NODES];
__device__ int   g_off[N_NODES];              // block-local exclusive offsets
__device__ int   g_bsum[98];
__device__ int   g_boff[98];
__device__ int   g_sorted[N_EDGES];
__device__ float g_gsum[N_GRAPHS * D];
__device__ float g_gcnt[N_GRAPHS];
__device__ float g_w3[4 * KDIM * NP];         // tf32-rounded packed weights

__constant__ int c_atom_off[9] = {0, 119, 124, 136, 148, 158, 164, 170, 172};

#define AVG_LOG_F 1.2465355243460002f
#define INV_BN    0.9999950000374997f

__device__ __forceinline__ float to_tf32(float x) {
    unsigned u;
    asm("cvt.rna.tf32.f32 %0, %1;" : "=r"(u) : "f"(x));
    return __uint_as_float(u);
}

__device__ __forceinline__ void mma_tf32(float c[4], unsigned a0, unsigned a1,
                                         unsigned a2, unsigned a3,
                                         unsigned b0, unsigned b1) {
    asm volatile(
        "mma.sync.aligned.m16n8k8.row.col.f32.tf32.tf32.f32 "
        "{%0,%1,%2,%3}, {%4,%5,%6,%7}, {%8,%9}, {%0,%1,%2,%3};\n"
        : "+f"(c[0]), "+f"(c[1]), "+f"(c[2]), "+f"(c[3])
        : "r"(a0), "r"(a1), "r"(a2), "r"(a3), "r"(b0), "r"(b1));
}

// ---------------- atom encoder + scratch zeroing (launch 1) ----------------
__global__ void atom_kernel(const int* __restrict__ x, const float* __restrict__ emb) {
    int flat = threadIdx.y * 70 + threadIdx.x;
    int gtid = blockIdx.x * 280 + flat;
    if (gtid < N_NODES) { g_cnt[gtid] = 0; g_cur[gtid] = 0; }
    if (gtid < N_GRAPHS * D) g_gsum[gtid] = 0.f;
    if (gtid < N_GRAPHS) g_gcnt[gtid] = 0.f;

    int n = blockIdx.x * blockDim.y + threadIdx.y;
    int f = threadIdx.x;
    if (n >= N_NODES) return;
    float s = 0.f;
#pragma unroll
    for (int j = 0; j < 9; j++) {
        int idx = x[n * 9 + j] + c_atom_off[j];
        s += emb[idx * D + f];
    }
    g_h[n * D + f] = s;
}

// ---------------- hist + W3 pack (launch 2) --------------------------------
// W3 layout: col c = half*120 + (p*5 + jr/8)*8 + jr%8, j = half*40 + jr  (j<70 real)
__global__ void hist_kernel(const int* __restrict__ ei, const float* __restrict__ W) {
    int gtid = blockIdx.x * blockDim.x + threadIdx.x;
    if (gtid < N_EDGES) atomicAdd(&g_cnt[ei[N_EDGES + gtid]], 1);
    if (gtid < 4 * KDIM * NP) {
        int l = gtid / (KDIM * NP);
        int rem = gtid - l * KDIM * NP;
        int k = rem / NP;
        int c = rem - k * NP;
        int half = c / 120;
        int cr = c - half * 120;
        int tile = cr >> 3;
        int u = cr & 7;
        int p = tile / 5;
        int jb = tile - p * 5;
        int j = half * 40 + jb * 8 + u;
        float v = 0.f;
        if (j < 70) v = to_tf32(W[((size_t)l * 840 + p * KDIM + k) * 70 + j]);
        g_w3[gtid] = v;
    }
}

// ---------------- scan: per-tile block scan + tiny top scan ----------------
__global__ void scanA_kernel() {   // 98 blocks x 1024
    __shared__ int ws[32];
    int t = threadIdx.x, lane = t & 31, wid = t >> 5;
    int i = blockIdx.x * 1024 + t;
    int v = (i < N_NODES) ? g_cnt[i] : 0;
    int x = v;
#pragma unroll
    for (int d = 1; d < 32; d <<= 1) {
        int y = __shfl_up_sync(0xffffffffu, x, d);
        if (lane >= d) x += y;
    }
    if (lane == 31) ws[wid] = x;
    __syncthreads();
    if (wid == 0) {
        int s = ws[lane];
#pragma unroll
        for (int d = 1; d < 32; d <<= 1) {
            int y = __shfl_up_sync(0xffffffffu, s, d);
            if (lane >= d) s += y;
        }
        ws[lane] = s;
    }
    __syncthreads();
    int base = (wid > 0) ? ws[wid - 1] : 0;
    if (i < N_NODES) g_off[i] = base + x - v;
    if (t == 1023) g_bsum[blockIdx.x] = base + x;
}

__global__ void scanB_kernel() {   // 1 block x 128
    __shared__ int ws[4];
    int t = threadIdx.x, lane = t & 31, wid = t >> 5;
    int v = (t < 98) ? g_bsum[t] : 0;
    int x = v;
#pragma unroll
    for (int d = 1; d < 32; d <<= 1) {
        int y = __shfl_up_sync(0xffffffffu, x, d);
        if (lane >= d) x += y;
    }
    if (lane == 31) ws[wid] = x;
    __syncthreads();
    int base = 0;
    for (int w = 0; w < wid; w++) base += ws[w];
    if (t < 98) g_boff[t] = base + x - v;
}

__global__ void scatter_kernel(const int* __restrict__ ei) {
    int e = blockIdx.x * blockDim.x + threadIdx.x;
    if (e < N_EDGES) {
        int d = ei[N_EDGES + e];
        int p = atomicAdd(&g_cur[d], 1);
        g_sorted[g_off[d] + g_boff[d >> 10] + p] = e;
    }
}

// ---------------- per-node aggregation (one warp per node) -----------------
__global__ void agg_kernel(const int* __restrict__ ei, const float* __restrict__ ea) {
    int gtid = blockIdx.x * blockDim.x + threadIdx.x;
    int node = gtid >> 5;
    int lane = gtid & 31;
    if (node >= N_NODES) return;

    const float* hrow = g_h + (size_t)node * D;
    float hd0 = hrow[lane];
    float hd1 = hrow[lane + 32];
    float hd2 = (lane < 6) ? hrow[lane + 64] : 0.f;

    int beg = g_off[node] + g_boff[node >> 10];
    int end = (node + 1 < N_NODES) ? (g_off[node + 1] + g_boff[(node + 1) >> 10]) : N_EDGES;

    float s0 = 0.f, s1 = 0.f, s2 = 0.f;
    float q0 = 0.f, q1 = 0.f, q2 = 0.f;
    float mn0 = 3.4e38f, mn1 = 3.4e38f, mn2 = 3.4e38f;
    float mx0 = 0.f, mx1 = 0.f, mx2 = 0.f;

    for (int p = beg; p < end; p++) {
        int e = g_sorted[p];
        int sn = ei[e];
        const float* hs = g_h + (size_t)sn * D;
        const float* er = ea + (size_t)e * D;
        float m0 = fmaxf(hd0 + hs[lane] + er[lane], 0.f);
        float m1 = fmaxf(hd1 + hs[lane + 32] + er[lane + 32], 0.f);
        float m2 = 0.f;
        if (lane < 6) m2 = fmaxf(hd2 + hs[lane + 64] + er[lane + 64], 0.f);
        s0 += m0; q0 += m0 * m0; mn0 = fminf(mn0, m0); mx0 = fmaxf(mx0, m0);
        s1 += m1; q1 += m1 * m1; mn1 = fminf(mn1, m1); mx1 = fmaxf(mx1, m1);
        s2 += m2; q2 += m2 * m2; mn2 = fminf(mn2, m2); mx2 = fmaxf(mx2, m2);
    }
    int cnt = end - beg;
    float cntf = (cnt > 0) ? (float)cnt : 1.f;

    float me0 = s0 / cntf, me1 = s1 / cntf, me2 = s2 / cntf;
    float v0 = fmaxf(q0 / cntf - me0 * me0, 0.f);
    float v1 = fmaxf(q1 / cntf - me1 * me1, 0.f);
    float v2 = fmaxf(q2 / cntf - me2 * me2, 0.f);
    float sd0 = sqrtf(v0 + 1e-5f), sd1 = sqrtf(v1 + 1e-5f), sd2 = sqrtf(v2 + 1e-5f);
    if (cnt == 0) { mn0 = mn1 = mn2 = 0.f; mx0 = mx1 = mx2 = 0.f; }

    float* a = g_agg + (size_t)node * (4 * D);
    a[lane]             = me0; a[lane + 32]         = me1;
    a[D + lane]         = mn0; a[D + lane + 32]     = mn1;
    a[2 * D + lane]     = mx0; a[2 * D + lane + 32] = mx1;
    a[3 * D + lane]     = sd0; a[3 * D + lane + 32] = sd1;
    if (lane < 6) {
        a[lane + 64]         = me2;
        a[D + lane + 64]     = mn2;
        a[2 * D + lane + 64] = mx2;
        a[3 * D + lane + 64] = sd2;
    }
    if (lane == 0) g_amp[node] = logf(cntf + 1.f) / AVG_LOG_F;
}

// ---------------- TF32 tensor-core GEMM + epilogue -------------------------
// [64 x 280] @ [280 x 240] per block; warps 4x2 (16 rows x 120 cols each)
#define GM 64
#define GK 40
__global__ __launch_bounds__(256, 2)
void gemm_kernel(int layer,
                 const float* __restrict__ b,
                 const float* __restrict__ gamma, const float* __restrict__ beta) {
    __shared__ float As[GM][GK];
    __shared__ float Bs[GK][NP];
    const float* W3 = g_w3 + (size_t)layer * KDIM * NP;
    int t = threadIdx.x;
    int lane = t & 31, wid = t >> 5;
    int wm = wid & 3, wn = wid >> 2;
    int row0 = blockIdx.x * GM;

    float c[15][4];
#pragma unroll
    for (int i = 0; i < 15; i++)
#pragma unroll
        for (int r = 0; r < 4; r++) c[i][r] = 0.f;

    const unsigned* Asu = reinterpret_cast<const unsigned*>(&As[0][0]);
    const unsigned* Bsu = reinterpret_cast<const unsigned*>(&Bs[0][0]);

    for (int kt = 0; kt < 7; kt++) {
        int k0 = kt * GK;
        for (int idx = t; idx < GM * GK; idx += 256) {
            int r = idx / GK, cc = idx - r * GK;
            int gr = row0 + r;
            float v = (gr < N_NODES) ? g_agg[(size_t)gr * KDIM + k0 + cc] : 0.f;
            As[r][cc] = to_tf32(v);
        }
        for (int idx = t; idx < GK * NP; idx += 256) {
            int r = idx / NP, cc = idx - r * NP;
            Bs[r][cc] = W3[(size_t)(k0 + r) * NP + cc];
        }
        __syncthreads();
#pragma unroll
        for (int ks = 0; ks < 5; ks++) {
            int k = ks * 8;
            int ar = wm * 16 + (lane >> 2);
            int ak = k + (lane & 3);
            unsigned a0 = Asu[ar * GK + ak];
            unsigned a1 = Asu[(ar + 8) * GK + ak];
            unsigned a2 = Asu[ar * GK + ak + 4];
            unsigned a3 = Asu[(ar + 8) * GK + ak + 4];
#pragma unroll
            for (int tile = 0; tile < 15; tile++) {
                int col = wn * 120 + tile * 8 + (lane >> 2);
                unsigned b0 = Bsu[(k + (lane & 3)) * NP + col];
                unsigned b1 = Bsu[(k + 4 + (lane & 3)) * NP + col];
                mma_tf32(c[tile], a0, a1, a2, a3, b0, b1);
            }
        }
        __syncthreads();
    }

    // epilogue: combine 3 panels with amp, bias, BN, relu, residual
    int r0 = row0 + wm * 16 + (lane >> 2);
    int r1 = r0 + 8;
    float amp0 = (r0 < N_NODES) ? g_amp[r0] : 1.f;
    float amp1 = (r1 < N_NODES) ? g_amp[r1] : 1.f;
#pragma unroll
    for (int jb = 0; jb < 5; jb++) {
#pragma unroll
        for (int cc = 0; cc < 2; cc++) {
            int j = wn * 40 + jb * 8 + (lane & 3) * 2 + cc;
            if (j < 70) {
                float bj = b[j], gj = gamma[j], btj = beta[j];
                if (r0 < N_NODES) {
                    float comb = c[jb][cc] + amp0 * c[5 + jb][cc] + c[10 + jb][cc] / amp0;
                    float hn = fmaxf((comb + bj) * INV_BN * gj + btj, 0.f);
                    g_h[(size_t)r0 * D + j] += hn;
                }
                if (r1 < N_NODES) {
                    float comb = c[jb][2 + cc] + amp1 * c[5 + jb][2 + cc] + c[10 + jb][2 + cc] / amp1;
                    float hn = fmaxf((comb + bj) * INV_BN * gj + btj, 0.f);
                    g_h[(size_t)r1 * D + j] += hn;
                }
            }
        }
    }
}

// ---------------- global mean pool -----------------------------------------
__global__ void pool_kernel(const int* __restrict__ batch) {
    int n = blockIdx.x * blockDim.y + threadIdx.y;
    int f = threadIdx.x;
    if (n >= N_NODES) return;
    int gi = batch[n];
    atomicAdd(&g_gsum[gi * D + f], g_h[(size_t)n * D + f]);
    if (f == 0) atomicAdd(&g_gcnt[gi], 1.f);
}

// ---------------- final MLP 70->35->17->1 ----------------------------------
__global__ void mlp_kernel(const float* __restrict__ w1, const float* __restrict__ b1,
                           const float* __restrict__ w2, const float* __restrict__ b2,
                           const float* __restrict__ w3, const float* __restrict__ b3,
                           float* __restrict__ out) {
    __shared__ float sg[70], t1[35], t2[17];
    int gi = blockIdx.x;
    int t = threadIdx.x;
    if (t < 70) {
        float cdenom = fmaxf(g_gcnt[gi], 1.f);
        sg[t] = g_gsum[gi * D + t] / cdenom;
    }
    __syncthreads();
    if (t < 35) {
        float s = b1[t];
        for (int k = 0; k < 70; k++) s += sg[k] * w1[k * 35 + t];
        t1[t] = fmaxf(s, 0.f);
    }
    __syncthreads();
    if (t < 17) {
        float s = b2[t];
        for (int k = 0; k < 35; k++) s += t1[k] * w2[k * 17 + t];
        t2[t] = fmaxf(s, 0.f);
    }
    __syncthreads();
    if (t == 0) {
        float s = b3[0];
        for (int k = 0; k < 17; k++) s += t2[k] * w3[k];
        out[gi] = s;
    }
}

// ---------------- launcher --------------------------------------------------
extern "C" void kernel_launch(void* const* d_in, const int* in_sizes, int n_in,
                              void* d_out, int out_size) {
    const int*   x      = (const int*)d_in[0];
    const int*   ei     = (const int*)d_in[1];
    const float* ea     = (const float*)d_in[2];
    const int*   batch  = (const int*)d_in[3];
    const float* emb    = (const float*)d_in[4];
    const float* post_w = (const float*)d_in[5];
    const float* post_b = (const float*)d_in[6];
    const float* gamma  = (const float*)d_in[7];
    const float* beta   = (const float*)d_in[8];
    const float* w1 = (const float*)d_in[9];
    const float* b1 = (const float*)d_in[10];
    const float* w2 = (const float*)d_in[11];
    const float* b2 = (const float*)d_in[12];
    const float* w3 = (const float*)d_in[13];
    const float* b3 = (const float*)d_in[14];
    float* out = (float*)d_out;

    atom_kernel<<<(N_NODES + 3) / 4, dim3(70, 4)>>>(x, emb);          // 1 (+ zero init)
    hist_kernel<<<(N_EDGES + 255) / 256, 256>>>(ei, post_w);          // 2 (+ W3 pack)
    scanA_kernel<<<98, 1024>>>();                                     // 3
    scanB_kernel<<<1, 128>>>();                                       // 4
    scatter_kernel<<<(N_EDGES + 255) / 256, 256>>>(ei);               // 5

    for (int l = 0; l < 4; l++) {
        agg_kernel<<<(N_NODES * 32 + 255) / 256, 256>>>(ei, ea);      // 6 = profiled (l=0)
        gemm_kernel<<<(N_NODES + GM - 1) / GM, 256>>>(
            l, post_b + l * 70, gamma + l * 70, beta + l * 70);
    }

    pool_kernel<<<(N_NODES + 3) / 4, dim3(70, 4)>>>(batch);
    mlp_kernel<<<N_GRAPHS, 70>>>(w1, b1, w2, b2, w3, b3, out);
}

// round 5
// speedup vs baseline: 2.0884x; 1.2207x over previous
#include <cuda_runtime.h>
#include <math.h>

#define N_NODES  100000
#define N_EDGES  400000
#define N_GRAPHS 4000
#define D        70
#define NP       240          // padded GEMM N (2 halves x (3 panels x 5 jb) x 8)
#define KDIM     280

// ---------------- scratch (device globals) ---------------------------------
__device__ float g_h[N_NODES * D];
__device__ float g_agg[N_NODES * 4 * D];      // [mean|min|max|std], K=280
__device__ float g_amp[N_NODES];
__device__ int   g_cnt[N_NODES];
__device__ int   g_cur[N_NODES];
__device__ int   g_off[N_NODES];              // block-local exclusive offsets
__device__ int   g_bsum[98];
__device__ int   g_boff[98];
__device__ int   g_sorted[N_EDGES];
__device__ float g_gsum[N_GRAPHS * D];
__device__ float g_gcnt[N_GRAPHS];
// packed tf32 weights, pair-permuted for LDS.64 frag loads:
// float2 index (per layer): ((kt*5 + g)*240 + col)*4 + l
//   holds (W[kt*40+g*8+l][col], W[kt*40+g*8+4+l][col])
__device__ float g_w3[4 * KDIM * NP];

__constant__ int c_atom_off[9] = {0, 119, 124, 136, 148, 158, 164, 170, 172};

#define AVG_LOG_F 1.2465355243460002f
#define INV_BN    0.9999950000374997f

__device__ __forceinline__ float to_tf32(float x) {
    unsigned u;
    asm("cvt.rna.tf32.f32 %0, %1;" : "=r"(u) : "f"(x));
    return __uint_as_float(u);
}

__device__ __forceinline__ void mma_tf32(float c[4], unsigned a0, unsigned a1,
                                         unsigned a2, unsigned a3,
                                         unsigned b0, unsigned b1) {
    asm volatile(
        "mma.sync.aligned.m16n8k8.row.col.f32.tf32.tf32.f32 "
        "{%0,%1,%2,%3}, {%4,%5,%6,%7}, {%8,%9}, {%0,%1,%2,%3};\n"
        : "+f"(c[0]), "+f"(c[1]), "+f"(c[2]), "+f"(c[3])
        : "r"(a0), "r"(a1), "r"(a2), "r"(a3), "r"(b0), "r"(b1));
}

// ---------------- atom encoder + scratch zeroing (launch 1) ----------------
__global__ void atom_kernel(const int* __restrict__ x, const float* __restrict__ emb) {
    int flat = threadIdx.y * 70 + threadIdx.x;
    int gtid = blockIdx.x * 280 + flat;
    if (gtid < N_NODES) { g_cnt[gtid] = 0; g_cur[gtid] = 0; }
    if (gtid < N_GRAPHS * D) g_gsum[gtid] = 0.f;
    if (gtid < N_GRAPHS) g_gcnt[gtid] = 0.f;

    int n = blockIdx.x * blockDim.y + threadIdx.y;
    int f = threadIdx.x;
    if (n >= N_NODES) return;
    float s = 0.f;
#pragma unroll
    for (int j = 0; j < 9; j++) {
        int idx = x[n * 9 + j] + c_atom_off[j];
        s += emb[idx * D + f];
    }
    g_h[n * D + f] = s;
}

// ---------------- hist + W3 pack (launch 2) --------------------------------
// Pack into the pair-permuted layout described at g_w3.
// col -> (panel p, output j):  half=col/120, cr=col%120, tile=cr/8, u=cr%8,
//                              p=tile/5, jb=tile%5, j=half*40+jb*8+u (<70 valid)
__global__ void hist_kernel(const int* __restrict__ ei, const float* __restrict__ W) {
    int gtid = blockIdx.x * blockDim.x + threadIdx.x;
    if (gtid < N_EDGES) atomicAdd(&g_cnt[ei[N_EDGES + gtid]], 1);
    if (gtid < 134400) {                      // 4 layers * 33600 float2
        int layer = gtid / 33600;
        int rem = gtid - layer * 33600;
        int kt = rem / 4800; rem -= kt * 4800;
        int g = rem / 960;   rem -= g * 960;
        int col = rem >> 2;
        int l = rem & 3;
        int half = col / 120;
        int cr = col - half * 120;
        int tile = cr >> 3;
        int u = cr & 7;
        int p = tile / 5;
        int jb = tile - p * 5;
        int j = half * 40 + jb * 8 + u;
        int kx = kt * 40 + g * 8 + l;
        float vx = 0.f, vy = 0.f;
        if (j < 70) {
            const float* Wl = W + (size_t)layer * 840 * 70;
            vx = to_tf32(Wl[(size_t)(p * KDIM + kx) * 70 + j]);
            vy = to_tf32(Wl[(size_t)(p * KDIM + kx + 4) * 70 + j]);
        }
        g_w3[gtid * 2]     = vx;
        g_w3[gtid * 2 + 1] = vy;
    }
}

// ---------------- scan: per-tile block scan + tiny top scan ----------------
__global__ void scanA_kernel() {   // 98 blocks x 1024
    __shared__ int ws[32];
    int t = threadIdx.x, lane = t & 31, wid = t >> 5;
    int i = blockIdx.x * 1024 + t;
    int v = (i < N_NODES) ? g_cnt[i] : 0;
    int x = v;
#pragma unroll
    for (int d = 1; d < 32; d <<= 1) {
        int y = __shfl_up_sync(0xffffffffu, x, d);
        if (lane >= d) x += y;
    }
    if (lane == 31) ws[wid] = x;
    __syncthreads();
    if (wid == 0) {
        int s = ws[lane];
#pragma unroll
        for (int d = 1; d < 32; d <<= 1) {
            int y = __shfl_up_sync(0xffffffffu, s, d);
            if (lane >= d) s += y;
        }
        ws[lane] = s;
    }
    __syncthreads();
    int base = (wid > 0) ? ws[wid - 1] : 0;
    if (i < N_NODES) g_off[i] = base + x - v;
    if (t == 1023) g_bsum[blockIdx.x] = base + x;
}

__global__ void scanB_kernel() {   // 1 block x 128
    __shared__ int ws[4];
    int t = threadIdx.x, lane = t & 31, wid = t >> 5;
    int v = (t < 98) ? g_bsum[t] : 0;
    int x = v;
#pragma unroll
    for (int d = 1; d < 32; d <<= 1) {
        int y = __shfl_up_sync(0xffffffffu, x, d);
        if (lane >= d) x += y;
    }
    if (lane == 31) ws[wid] = x;
    __syncthreads();
    int base = 0;
    for (int w = 0; w < wid; w++) base += ws[w];
    if (t < 98) g_boff[t] = base + x - v;
}

__global__ void scatter_kernel(const int* __restrict__ ei) {
    int e = blockIdx.x * blockDim.x + threadIdx.x;
    if (e < N_EDGES) {
        int d = ei[N_EDGES + e];
        int p = atomicAdd(&g_cur[d], 1);
        g_sorted[g_off[d] + g_boff[d >> 10] + p] = e;
    }
}

// ---------------- per-node aggregation (one warp per node) -----------------
// float2-vectorized: lane covers feats {2l, 2l+1}; lanes 0..2 also {64+2l, 65+2l}
__global__ void agg_kernel(const int* __restrict__ ei, const float* __restrict__ ea) {
    int gtid = blockIdx.x * blockDim.x + threadIdx.x;
    int node = gtid >> 5;
    int lane = gtid & 31;
    if (node >= N_NODES) return;

    const float2* hrow = (const float2*)(g_h + (size_t)node * D);
    float2 hm = hrow[lane];
    float2 ht = make_float2(0.f, 0.f);
    if (lane < 3) ht = hrow[32 + lane];

    int beg = g_off[node] + g_boff[node >> 10];
    int end = (node + 1 < N_NODES) ? (g_off[node + 1] + g_boff[(node + 1) >> 10]) : N_EDGES;

    float2 s  = make_float2(0.f, 0.f), q  = make_float2(0.f, 0.f);
    float2 mn = make_float2(3.4e38f, 3.4e38f), mx = make_float2(0.f, 0.f);
    float2 st = make_float2(0.f, 0.f), qt = make_float2(0.f, 0.f);
    float2 mnt = make_float2(3.4e38f, 3.4e38f), mxt = make_float2(0.f, 0.f);

    int e = 0, sn = 0;
    if (beg < end) { e = g_sorted[beg]; sn = ei[e]; }
    for (int p = beg; p < end; p++) {
        const float2* hs = (const float2*)(g_h + (size_t)sn * D);
        const float2* er = (const float2*)(ea + (size_t)e * D);
        float2 a = hs[lane];
        float2 b2 = er[lane];
        float2 at = make_float2(0.f, 0.f), bt = make_float2(0.f, 0.f);
        if (lane < 3) { at = hs[32 + lane]; bt = er[32 + lane]; }
        // prefetch next edge's indices (breaks the dependent-load chain)
        int pn = p + 1;
        if (pn < end) { e = g_sorted[pn]; sn = ei[e]; }

        float m0 = fmaxf(hm.x + a.x + b2.x, 0.f);
        float m1 = fmaxf(hm.y + a.y + b2.y, 0.f);
        s.x += m0; q.x += m0 * m0; mn.x = fminf(mn.x, m0); mx.x = fmaxf(mx.x, m0);
        s.y += m1; q.y += m1 * m1; mn.y = fminf(mn.y, m1); mx.y = fmaxf(mx.y, m1);
        if (lane < 3) {
            float t0 = fmaxf(ht.x + at.x + bt.x, 0.f);
            float t1 = fmaxf(ht.y + at.y + bt.y, 0.f);
            st.x += t0; qt.x += t0 * t0; mnt.x = fminf(mnt.x, t0); mxt.x = fmaxf(mxt.x, t0);
            st.y += t1; qt.y += t1 * t1; mnt.y = fminf(mnt.y, t1); mxt.y = fmaxf(mxt.y, t1);
        }
    }
    int cnt = end - beg;
    float cf = (cnt > 0) ? (float)cnt : 1.f;
    float inv = 1.f / cf;

    float2 me = make_float2(s.x * inv, s.y * inv);
    float2 sd;
    sd.x = sqrtf(fmaxf(q.x * inv - me.x * me.x, 0.f) + 1e-5f);
    sd.y = sqrtf(fmaxf(q.y * inv - me.y * me.y, 0.f) + 1e-5f);
    float2 met = make_float2(st.x * inv, st.y * inv);
    float2 sdt;
    sdt.x = sqrtf(fmaxf(qt.x * inv - met.x * met.x, 0.f) + 1e-5f);
    sdt.y = sqrtf(fmaxf(qt.y * inv - met.y * met.y, 0.f) + 1e-5f);
    if (cnt == 0) {
        mn = make_float2(0.f, 0.f); mx = make_float2(0.f, 0.f);
        mnt = make_float2(0.f, 0.f); mxt = make_float2(0.f, 0.f);
    }

    float2* arow = (float2*)(g_agg + (size_t)node * (4 * D));
    arow[lane]            = me;   // mean   floats [0,70)
    arow[35 + lane]       = mn;   // min    floats [70,140)
    arow[70 + lane]       = mx;   // max    floats [140,210)
    arow[105 + lane]      = sd;   // std    floats [210,280)
    if (lane < 3) {
        arow[32 + lane]       = met;
        arow[35 + 32 + lane]  = mnt;
        arow[70 + 32 + lane]  = mxt;
        arow[105 + 32 + lane] = sdt;
    }
    if (lane == 0) g_amp[node] = logf(cf + 1.f) / AVG_LOG_F;
}

// ---------------- TF32 tensor-core GEMM + epilogue -------------------------
// [64 x 280] @ [280 x 240] per block; warps 4x2 (16 rows x 120 cols each).
// Pair-permuted smem: every MMA fragment is one conflict-free LDS.64.
#define GM 64
__global__ __launch_bounds__(256, 2)
void gemm_kernel(int layer,
                 const float* __restrict__ b,
                 const float* __restrict__ gamma, const float* __restrict__ beta) {
    __shared__ float2 As2[5 * 64 * 4];    // [g][row][l] = (A[r][8g+l], A[r][8g+4+l])
    __shared__ float2 Bs2[5 * 240 * 4];   // [g][col][l] = (W[8g+l][c], W[8g+4+l][c])
    const float* W3 = g_w3 + (size_t)layer * (KDIM * NP);
    int t = threadIdx.x;
    int lane = t & 31, wid = t >> 5;
    int wm = wid & 3, wn = wid >> 2;
    int row0 = blockIdx.x * GM;

    float c[15][4];
#pragma unroll
    for (int i = 0; i < 15; i++)
#pragma unroll
        for (int r = 0; r < 4; r++) c[i][r] = 0.f;

    float* As_f = (float*)As2;
    float4* Bs4 = (float4*)Bs2;

    for (int kt = 0; kt < 7; kt++) {
        int k0 = kt * 40;
        // A fill: 64 rows x 10 float4 (k-major), scatter into pair layout
        for (int idx = t; idx < 640; idx += 256) {
            int r = idx / 10, qq = idx - r * 10;
            int gr = row0 + r;
            float4 v = make_float4(0.f, 0.f, 0.f, 0.f);
            if (gr < N_NODES)
                v = *(const float4*)(g_agg + (size_t)gr * KDIM + k0 + qq * 4);
            int g = qq >> 1, sslot = qq & 1;
            int base = (g * 64 + r) * 8 + sslot;  // float index of [g][r][0].(x|y)
            As_f[base + 0] = to_tf32(v.x);
            As_f[base + 2] = to_tf32(v.y);
            As_f[base + 4] = to_tf32(v.z);
            As_f[base + 6] = to_tf32(v.w);
        }
        // B fill: straight float4 copy (prepacked layout == smem layout)
        const float4* Wg = (const float4*)(W3 + kt * 9600);
        for (int idx = t; idx < 2400; idx += 256) Bs4[idx] = Wg[idx];
        __syncthreads();
#pragma unroll
        for (int g = 0; g < 5; g++) {
            float2 A0 = As2[(g * 64 + wm * 16 + (lane >> 2)) * 4 + (lane & 3)];
            float2 A1 = As2[(g * 64 + wm * 16 + 8 + (lane >> 2)) * 4 + (lane & 3)];
            unsigned a0 = __float_as_uint(A0.x), a1 = __float_as_uint(A1.x);
            unsigned a2 = __float_as_uint(A0.y), a3 = __float_as_uint(A1.y);
#pragma unroll
            for (int tile = 0; tile < 15; tile++) {
                float2 Bv = Bs2[(g * 240 + wn * 120 + tile * 8 + (lane >> 2)) * 4 + (lane & 3)];
                mma_tf32(c[tile], a0, a1, a2, a3,
                         __float_as_uint(Bv.x), __float_as_uint(Bv.y));
            }
        }
        __syncthreads();
    }

    // epilogue: combine 3 panels with amp, bias, BN, relu, residual
    int r0 = row0 + wm * 16 + (lane >> 2);
    int r1 = r0 + 8;
    float amp0 = (r0 < N_NODES) ? g_amp[r0] : 1.f;
    float amp1 = (r1 < N_NODES) ? g_amp[r1] : 1.f;
#pragma unroll
    for (int jb = 0; jb < 5; jb++) {
#pragma unroll
        for (int cc = 0; cc < 2; cc++) {
            int j = wn * 40 + jb * 8 + (lane & 3) * 2 + cc;
            if (j < 70) {
                float bj = b[j], gj = gamma[j], btj = beta[j];
                if (r0 < N_NODES) {
                    float comb = c[jb][cc] + amp0 * c[5 + jb][cc] + c[10 + jb][cc] / amp0;
                    float hn = fmaxf((comb + bj) * INV_BN * gj + btj, 0.f);
                    g_h[(size_t)r0 * D + j] += hn;
                }
                if (r1 < N_NODES) {
                    float comb = c[jb][2 + cc] + amp1 * c[5 + jb][2 + cc] + c[10 + jb][2 + cc] / amp1;
                    float hn = fmaxf((comb + bj) * INV_BN * gj + btj, 0.f);
                    g_h[(size_t)r1 * D + j] += hn;
                }
            }
        }
    }
}

// ---------------- global mean pool -----------------------------------------
__global__ void pool_kernel(const int* __restrict__ batch) {
    int n = blockIdx.x * blockDim.y + threadIdx.y;
    int f = threadIdx.x;
    if (n >= N_NODES) return;
    int gi = batch[n];
    atomicAdd(&g_gsum[gi * D + f], g_h[(size_t)n * D + f]);
    if (f == 0) atomicAdd(&g_gcnt[gi], 1.f);
}

// ---------------- final MLP 70->35->17->1 ----------------------------------
__global__ void mlp_kernel(const float* __restrict__ w1, const float* __restrict__ b1,
                           const float* __restrict__ w2, const float* __restrict__ b2,
                           const float* __restrict__ w3, const float* __restrict__ b3,
                           float* __restrict__ out) {
    __shared__ float sg[70], t1[35], t2[17];
    int gi = blockIdx.x;
    int t = threadIdx.x;
    if (t < 70) {
        float cdenom = fmaxf(g_gcnt[gi], 1.f);
        sg[t] = g_gsum[gi * D + t] / cdenom;
    }
    __syncthreads();
    if (t < 35) {
        float s = b1[t];
        for (int k = 0; k < 70; k++) s += sg[k] * w1[k * 35 + t];
        t1[t] = fmaxf(s, 0.f);
    }
    __syncthreads();
    if (t < 17) {
        float s = b2[t];
        for (int k = 0; k < 35; k++) s += t1[k] * w2[k * 17 + t];
        t2[t] = fmaxf(s, 0.f);
    }
    __syncthreads();
    if (t == 0) {
        float s = b3[0];
        for (int k = 0; k < 17; k++) s += t2[k] * w3[k];
        out[gi] = s;
    }
}

// ---------------- launcher --------------------------------------------------
extern "C" void kernel_launch(void* const* d_in, const int* in_sizes, int n_in,
                              void* d_out, int out_size) {
    const int*   x      = (const int*)d_in[0];
    const int*   ei     = (const int*)d_in[1];
    const float* ea     = (const float*)d_in[2];
    const int*   batch  = (const int*)d_in[3];
    const float* emb    = (const float*)d_in[4];
    const float* post_w = (const float*)d_in[5];
    const float* post_b = (const float*)d_in[6];
    const float* gamma  = (const float*)d_in[7];
    const float* beta   = (const float*)d_in[8];
    const float* w1 = (const float*)d_in[9];
    const float* b1 = (const float*)d_in[10];
    const float* w2 = (const float*)d_in[11];
    const float* b2 = (const float*)d_in[12];
    const float* w3 = (const float*)d_in[13];
    const float* b3 = (const float*)d_in[14];
    float* out = (float*)d_out;

    atom_kernel<<<(N_NODES + 3) / 4, dim3(70, 4)>>>(x, emb);          // 1 (+ zero init)
    hist_kernel<<<(N_EDGES + 255) / 256, 256>>>(ei, post_w);          // 2 (+ W3 pack)
    scanA_kernel<<<98, 1024>>>();                                     // 3
    scanB_kernel<<<1, 128>>>();                                       // 4 (profiled slot)
    scatter_kernel<<<(N_EDGES + 255) / 256, 256>>>(ei);               // 5

    for (int l = 0; l < 4; l++) {
        agg_kernel<<<(N_NODES * 32 + 255) / 256, 256>>>(ei, ea);
        gemm_kernel<<<(N_NODES + GM - 1) / GM, 256>>>(
            l, post_b + l * 70, gamma + l * 70, beta + l * 70);
    }

    pool_kernel<<<(N_NODES + 3) / 4, dim3(70, 4)>>>(batch);
    mlp_kernel<<<N_GRAPHS, 70>>>(w1, b1, w2, b2, w3, b3, out);
}